// round 1
// baseline (speedup 1.0000x reference)
#include <cuda_runtime.h>
#include <math.h>
#include <float.h>

#define BB 4
#define TT 1024
#define CCH 1024
#define HH 16
#define LLAT 256
#define DD 64

// ---------------- scratch (static device globals; no allocations allowed) ----
__device__ float g_kv_down[BB * TT * LLAT];
__device__ float g_q_down [BB * TT * LLAT];
__device__ float g_kbuf   [BB * TT * CCH];
__device__ float g_qbuf   [BB * TT * CCH];
__device__ float g_vbuf   [BB * TT * CCH];
__device__ float g_ctx    [BB * TT * CCH];
__device__ float g_imt    [(size_t)BB * HH * TT * TT];   // 256 MB transposed interaction

// ---------------- generic fp32 SGEMM: C[M,N] = A[M,K] @ B[K,N] (+bias) -------
// Requires M%128==0, N%128==0, K%16==0 (true for every call here).
__global__ __launch_bounds__(256) void sgemm128(
    const float* __restrict__ A, const float* __restrict__ Bm,
    float* __restrict__ Cm, const float* __restrict__ bias,
    int M, int N, int K)
{
    __shared__ float As[16][128];   // transposed: As[k][m]
    __shared__ float Bs[16][128];   // Bs[k][n]

    const int tid = threadIdx.x;
    const int tx = tid & 15, ty = tid >> 4;
    const int m0 = blockIdx.y * 128, n0 = blockIdx.x * 128;

    float acc[8][8];
#pragma unroll
    for (int i = 0; i < 8; i++)
#pragma unroll
        for (int j = 0; j < 8; j++) acc[i][j] = 0.f;

    const int ar = tid >> 2;            // 0..63
    const int ac = (tid & 3) * 4;       // 0,4,8,12
    const int br = tid >> 5;            // 0..7
    const int bc = (tid & 31) * 4;      // 0..124

    for (int k0 = 0; k0 < K; k0 += 16) {
#pragma unroll
        for (int it = 0; it < 2; it++) {
            int r = ar + it * 64;
            float4 av = *(const float4*)&A[(size_t)(m0 + r) * K + k0 + ac];
            As[ac + 0][r] = av.x; As[ac + 1][r] = av.y;
            As[ac + 2][r] = av.z; As[ac + 3][r] = av.w;
            int rb = br + it * 8;
            float4 bv = *(const float4*)&Bm[(size_t)(k0 + rb) * N + n0 + bc];
            *(float4*)&Bs[rb][bc] = bv;
        }
        __syncthreads();
#pragma unroll
        for (int kk = 0; kk < 16; kk++) {
            float a[8], bf[8];
            *(float4*)&a[0]  = *(const float4*)&As[kk][ty * 8];
            *(float4*)&a[4]  = *(const float4*)&As[kk][ty * 8 + 4];
            *(float4*)&bf[0] = *(const float4*)&Bs[kk][tx * 8];
            *(float4*)&bf[4] = *(const float4*)&Bs[kk][tx * 8 + 4];
#pragma unroll
            for (int i = 0; i < 8; i++)
#pragma unroll
                for (int j = 0; j < 8; j++)
                    acc[i][j] = fmaf(a[i], bf[j], acc[i][j]);
        }
        __syncthreads();
    }

#pragma unroll
    for (int i = 0; i < 8; i++) {
        int m = m0 + ty * 8 + i;
#pragma unroll
        for (int j = 0; j < 8; j += 4) {
            int n = n0 + tx * 8 + j;
            float4 o;
            o.x = acc[i][j + 0]; o.y = acc[i][j + 1];
            o.z = acc[i][j + 2]; o.w = acc[i][j + 3];
            if (bias) {
                o.x += bias[n];     o.y += bias[n + 1];
                o.z += bias[n + 2]; o.w += bias[n + 3];
            }
            *(float4*)&Cm[(size_t)m * N + n] = o;
        }
    }
}

// ------------- transpose interaction [b,k,q,h] -> imt[b,h,q,k] --------------
// Block handles (b, 32 k, 32 q, all 16 h). Reads contiguous (q,h), writes
// contiguous k. smem pitch 33 avoids bank conflicts.
__global__ __launch_bounds__(256) void transpose_im(const float* __restrict__ im)
{
    extern __shared__ float s[];   // [512][33] : s[(qq*16+h)*33 + kk]
    const int tid = threadIdx.x;
    const int k0 = blockIdx.x * 32;
    const int q0 = blockIdx.y * 32;
    const int b  = blockIdx.z;
    const float* inb = im + (size_t)b * TT * TT * HH;

#pragma unroll 8
    for (int step = 0; step < 64; step++) {
        int i = tid + step * 256;          // 0..16383
        int kk   = i >> 9;                 // /512
        int rest = i & 511;                // qq*16+h
        s[rest * 33 + kk] = inb[(size_t)(k0 + kk) * (TT * HH) + q0 * HH + rest];
    }
    __syncthreads();
#pragma unroll 8
    for (int step = 0; step < 64; step++) {
        int o = tid + step * 256;
        int row = o >> 5;                  // qq*16+h
        int kk  = o & 31;
        int h  = row & 15, qq = row >> 4;
        g_imt[((size_t)(b * HH + h) * TT + q0 + qq) * TT + k0 + kk] = s[row * 33 + kk];
    }
}

// ------------------- flash attention (fp32, causal, +imt) -------------------
// Block = (b, h, 64-row q tile). 256 threads as 16x16; each thread owns a
// 4(q) x 4(k or d) microtile. Online softmax state fully in registers.
__global__ __launch_bounds__(256, 2) void attn_kernel(const int* __restrict__ pad_mask)
{
    extern __shared__ float sm[];
    float* Qst = sm;                 // [d][q]  pitch 68 (pre-scaled by 1/sqrt(D))
    float* Kst = sm + 64 * 68;       // [d][k]  pitch 68
    float* Vs  = sm + 2 * 64 * 68;   // [k][d]  pitch 68
    float* Ps  = sm + 3 * 64 * 68;   // [q][k]  pitch 68

    const int tid = threadIdx.x;
    const int tx = tid & 15, ty = tid >> 4;
    const int qt = blockIdx.x, h = blockIdx.y, b = blockIdx.z;
    const int q0 = qt * 64;
    const float scale = 0.125f;      // D^-0.5, D=64

    // ---- load Q tile (transposed into smem, pre-scaled) ----
#pragma unroll
    for (int it = 0; it < 4; it++) {
        int i = tid + it * 256;          // float4 unit 0..1023
        int row = i >> 4;                // q 0..63
        int c4  = (i & 15) * 4;          // d
        float4 qv = *(const float4*)&g_qbuf[((size_t)(b * TT + q0 + row)) * CCH + h * DD + c4];
        Qst[(c4 + 0) * 68 + row] = qv.x * scale;
        Qst[(c4 + 1) * 68 + row] = qv.y * scale;
        Qst[(c4 + 2) * 68 + row] = qv.z * scale;
        Qst[(c4 + 3) * 68 + row] = qv.w * scale;
    }

    int rowpad[4];
#pragma unroll
    for (int i = 0; i < 4; i++) rowpad[i] = pad_mask[b * TT + q0 + ty * 4 + i];

    float m_i[4], l_i[4], acc[4][4];
#pragma unroll
    for (int i = 0; i < 4; i++) {
        m_i[i] = -INFINITY; l_i[i] = 0.f;
#pragma unroll
        for (int j = 0; j < 4; j++) acc[i][j] = 0.f;
    }

    const size_t im_base = (size_t)(b * HH + h) * TT * TT;
    const int nkt = qt + 1;              // causal: only k tiles with k0 <= q0

    for (int kt = 0; kt < nkt; kt++) {
        const int k0 = kt * 64;
        // ---- stage K (transposed) and V ----
#pragma unroll
        for (int it = 0; it < 4; it++) {
            int i = tid + it * 256;
            int row = i >> 4;
            int c4  = (i & 15) * 4;
            size_t g = ((size_t)(b * TT + k0 + row)) * CCH + h * DD + c4;
            float4 kv = *(const float4*)&g_kbuf[g];
            Kst[(c4 + 0) * 68 + row] = kv.x;
            Kst[(c4 + 1) * 68 + row] = kv.y;
            Kst[(c4 + 2) * 68 + row] = kv.z;
            Kst[(c4 + 3) * 68 + row] = kv.w;
            float4 vv = *(const float4*)&g_vbuf[g];
            *(float4*)&Vs[row * 68 + c4] = vv;
        }
        __syncthreads();

        // ---- S = Q K^T (scaled) ----
        float s4[4][4];
#pragma unroll
        for (int i = 0; i < 4; i++)
#pragma unroll
            for (int j = 0; j < 4; j++) s4[i][j] = 0.f;
#pragma unroll
        for (int d = 0; d < 64; d++) {
            float4 a4 = *(const float4*)&Qst[d * 68 + ty * 4];
            float4 b4 = *(const float4*)&Kst[d * 68 + tx * 4];
            float a[4] = {a4.x, a4.y, a4.z, a4.w};
            float bb[4] = {b4.x, b4.y, b4.z, b4.w};
#pragma unroll
            for (int i = 0; i < 4; i++)
#pragma unroll
                for (int j = 0; j < 4; j++)
                    s4[i][j] = fmaf(a[i], bb[j], s4[i][j]);
        }

        // ---- padding mask, causal mask, + interaction ----
#pragma unroll
        for (int i = 0; i < 4; i++) {
            int q = q0 + ty * 4 + i;
            float4 im4 = *(const float4*)&g_imt[im_base + (size_t)q * TT + k0 + tx * 4];
            float imv[4] = {im4.x, im4.y, im4.z, im4.w};
#pragma unroll
            for (int j = 0; j < 4; j++) {
                int k = k0 + tx * 4 + j;
                float v = rowpad[i] ? s4[i][j] : -1e9f;
                v = (k <= q) ? v : -INFINITY;
                s4[i][j] = v + imv[j];
            }
        }

        // ---- online softmax (row reductions over 16-lane groups) ----
#pragma unroll
        for (int i = 0; i < 4; i++) {
            float rm = fmaxf(fmaxf(s4[i][0], s4[i][1]), fmaxf(s4[i][2], s4[i][3]));
#pragma unroll
            for (int msk = 1; msk < 16; msk <<= 1)
                rm = fmaxf(rm, __shfl_xor_sync(0xffffffffu, rm, msk));
            float m_new = fmaxf(m_i[i], rm);
            float alpha = __expf(m_i[i] - m_new);
            float rs = 0.f;
#pragma unroll
            for (int j = 0; j < 4; j++) {
                float p = __expf(s4[i][j] - m_new);
                s4[i][j] = p;
                rs += p;
            }
#pragma unroll
            for (int msk = 1; msk < 16; msk <<= 1)
                rs += __shfl_xor_sync(0xffffffffu, rs, msk);
            l_i[i] = l_i[i] * alpha + rs;
            m_i[i] = m_new;
#pragma unroll
            for (int j = 0; j < 4; j++) acc[i][j] *= alpha;
        }

        // ---- P to smem, O += P V ----
#pragma unroll
        for (int i = 0; i < 4; i++) {
            float4 pv;
            pv.x = s4[i][0]; pv.y = s4[i][1]; pv.z = s4[i][2]; pv.w = s4[i][3];
            *(float4*)&Ps[(ty * 4 + i) * 68 + tx * 4] = pv;
        }
        __syncthreads();
#pragma unroll
        for (int k = 0; k < 64; k++) {
            float4 v4 = *(const float4*)&Vs[k * 68 + tx * 4];
            float vv[4] = {v4.x, v4.y, v4.z, v4.w};
            float p0 = Ps[(ty * 4 + 0) * 68 + k];
            float p1 = Ps[(ty * 4 + 1) * 68 + k];
            float p2 = Ps[(ty * 4 + 2) * 68 + k];
            float p3 = Ps[(ty * 4 + 3) * 68 + k];
#pragma unroll
            for (int j = 0; j < 4; j++) {
                acc[0][j] = fmaf(p0, vv[j], acc[0][j]);
                acc[1][j] = fmaf(p1, vv[j], acc[1][j]);
                acc[2][j] = fmaf(p2, vv[j], acc[2][j]);
                acc[3][j] = fmaf(p3, vv[j], acc[3][j]);
            }
        }
        __syncthreads();   // before next tile overwrites Kst/Vs/Ps
    }

    // ---- epilogue: ctx = O / l ----
#pragma unroll
    for (int i = 0; i < 4; i++) {
        float inv = 1.f / l_i[i];
        float4 o;
        o.x = acc[i][0] * inv; o.y = acc[i][1] * inv;
        o.z = acc[i][2] * inv; o.w = acc[i][3] * inv;
        *(float4*)&g_ctx[((size_t)(b * TT + q0 + ty * 4 + i)) * CCH + h * DD + tx * 4] = o;
    }
}

// ----------------------------- host launcher --------------------------------
extern "C" void kernel_launch(void* const* d_in, const int* in_sizes, int n_in,
                              void* d_out, int out_size)
{
    const float* x       = (const float*)d_in[0];
    const int*   pad     = (const int*)  d_in[1];
    const float* im      = (const float*)d_in[2];
    const float* W_ckv   = (const float*)d_in[3];
    const float* W_cq    = (const float*)d_in[4];
    const float* W_kc    = (const float*)d_in[5];
    const float* W_qc    = (const float*)d_in[6];
    const float* W_vc    = (const float*)d_in[7];
    const float* W_proj  = (const float*)d_in[8];
    const float* b_proj  = (const float*)d_in[9];
    float* out = (float*)d_out;

    float *kv_down, *q_down, *kbuf, *qbuf, *vbuf, *ctx;
    cudaGetSymbolAddress((void**)&kv_down, g_kv_down);
    cudaGetSymbolAddress((void**)&q_down,  g_q_down);
    cudaGetSymbolAddress((void**)&kbuf,    g_kbuf);
    cudaGetSymbolAddress((void**)&qbuf,    g_qbuf);
    cudaGetSymbolAddress((void**)&vbuf,    g_vbuf);
    cudaGetSymbolAddress((void**)&ctx,     g_ctx);

    cudaFuncSetAttribute(transpose_im, cudaFuncAttributeMaxDynamicSharedMemorySize,
                         512 * 33 * 4);
    cudaFuncSetAttribute(attn_kernel, cudaFuncAttributeMaxDynamicSharedMemorySize,
                         4 * 64 * 68 * 4);

    const int M = BB * TT;   // 4096

    // interaction transpose (independent of GEMM chain)
    transpose_im<<<dim3(32, 32, 4), 256, 512 * 33 * 4>>>(im);

    // down projections: [4096,1024] @ [1024,256]
    sgemm128<<<dim3(LLAT / 128, M / 128), 256>>>(x, W_ckv, kv_down, nullptr, M, LLAT, CCH);
    sgemm128<<<dim3(LLAT / 128, M / 128), 256>>>(x, W_cq,  q_down,  nullptr, M, LLAT, CCH);

    // up projections: [4096,256] @ [256,1024]
    sgemm128<<<dim3(CCH / 128, M / 128), 256>>>(kv_down, W_kc, kbuf, nullptr, M, CCH, LLAT);
    sgemm128<<<dim3(CCH / 128, M / 128), 256>>>(q_down,  W_qc, qbuf, nullptr, M, CCH, LLAT);
    sgemm128<<<dim3(CCH / 128, M / 128), 256>>>(kv_down, W_vc, vbuf, nullptr, M, CCH, LLAT);

    // attention
    attn_kernel<<<dim3(TT / 64, HH, BB), 256, 4 * 64 * 68 * 4>>>(pad);

    // output projection + bias: [4096,1024] @ [1024,1024]
    sgemm128<<<dim3(CCH / 128, M / 128), 256>>>(ctx, W_proj, out, b_proj, M, CCH, CCH);
}

// round 5
// speedup vs baseline: 1.5795x; 1.5795x over previous
#include <cuda_runtime.h>
#include <math.h>
#include <float.h>
#include <stdint.h>

#define BB 4
#define TT 1024
#define CCH 1024
#define HH 16
#define LLAT 256
#define DD 64

// ---------------- scratch (static device globals; no allocations allowed) ----
__device__ float g_kv_down[BB * TT * LLAT];
__device__ float g_q_down [BB * TT * LLAT];
__device__ float g_kbuf   [BB * TT * CCH];
__device__ float g_qbuf   [BB * TT * CCH];
__device__ float g_vbuf   [BB * TT * CCH];
__device__ float g_ctx    [BB * TT * CCH];
__device__ float g_imt    [(size_t)BB * HH * TT * TT];   // 256 MB transposed interaction

// ---------------------------- tf32 helpers ----------------------------------
__device__ __forceinline__ uint32_t f2tf32(float x) {
    uint32_t r;
    asm("cvt.rna.tf32.f32 %0, %1;" : "=r"(r) : "f"(x));
    return r;
}

__device__ __forceinline__ void ldsm_x4(uint32_t& r0, uint32_t& r1, uint32_t& r2,
                                        uint32_t& r3, uint32_t addr) {
    asm volatile("ldmatrix.sync.aligned.m8n8.x4.shared.b16 {%0,%1,%2,%3}, [%4];"
                 : "=r"(r0), "=r"(r1), "=r"(r2), "=r"(r3) : "r"(addr));
}

__device__ __forceinline__ void mma_tf32(float* d, uint32_t a0, uint32_t a1,
                                         uint32_t a2, uint32_t a3,
                                         uint32_t b0, uint32_t b1) {
    asm volatile(
        "mma.sync.aligned.m16n8k8.row.col.f32.tf32.tf32.f32 "
        "{%0,%1,%2,%3}, {%4,%5,%6,%7}, {%8,%9}, {%0,%1,%2,%3};"
        : "+f"(d[0]), "+f"(d[1]), "+f"(d[2]), "+f"(d[3])
        : "r"(a0), "r"(a1), "r"(a2), "r"(a3), "r"(b0), "r"(b1));
}

// ---------------- tf32 tensor-core GEMM: C[M,N] = A[M,K] @ B[K,N] (+bias) ----
// Tile 128x128, k-chunk 32. 8 warps as 2(m) x 4(n); warp tile 64x32.
// Requires M%128==0, N%128==0, K%32==0 (true for every call here).
#define APITCH 36
__global__ __launch_bounds__(256) void gemm_tf32(
    const float* __restrict__ A, const float* __restrict__ Bm,
    float* __restrict__ Cm, const float* __restrict__ bias,
    int M, int N, int K)
{
    __shared__ uint32_t As [128 * APITCH];   // [m][k] pitch 36 (tf32 bits)
    __shared__ uint32_t Bsn[128 * APITCH];   // [n][k] pitch 36 (tf32 bits)

    const int tid  = threadIdx.x;
    const int lane = tid & 31;
    const int warp = tid >> 5;
    const int m0 = blockIdx.y * 128, n0 = blockIdx.x * 128;
    const int m0w = (warp >> 2) * 64;
    const int n0w = (warp & 3) * 32;

    // staging index precompute
    const int am  = tid >> 3;         // 0..31   (A row group)
    const int akq = tid & 7;          // 0..7    (A k-quad)
    const int bn  = tid & 127;        // 0..127  (B n)
    const int bkq = tid >> 7;         // 0..1    (B k-quad base)

    // ldmatrix per-lane offsets
    const int a_row = m0w + (lane & 15);
    const int a_k   = (lane >> 4) * 4;
    const int b_row = n0w + (lane & 7) + ((lane >> 4) & 1) * 8;
    const int b_k   = ((lane >> 3) & 1) * 4;

    const uint32_t as_base = (uint32_t)__cvta_generic_to_shared(As);
    const uint32_t bs_base = (uint32_t)__cvta_generic_to_shared(Bsn);

    float acc[4][4][4];
#pragma unroll
    for (int i = 0; i < 4; i++)
#pragma unroll
        for (int j = 0; j < 4; j++)
#pragma unroll
            for (int r = 0; r < 4; r++) acc[i][j][r] = 0.f;

    for (int k0 = 0; k0 < K; k0 += 32) {
        // ---- stage A: 128 x 32, float4 along k, cvt to tf32 ----
#pragma unroll
        for (int it = 0; it < 4; it++) {
            int row = am + it * 32;
            float4 v = *(const float4*)&A[(size_t)(m0 + row) * K + k0 + akq * 4];
            uint4 t;
            t.x = f2tf32(v.x); t.y = f2tf32(v.y);
            t.z = f2tf32(v.z); t.w = f2tf32(v.w);
            *(uint4*)&As[row * APITCH + akq * 4] = t;
        }
        // ---- stage B transposed: Bsn[n][k], 4 strided global reads per quad ----
#pragma unroll
        for (int it = 0; it < 4; it++) {
            int kq = bkq + it * 2;
            const float* src = &Bm[(size_t)(k0 + kq * 4) * N + n0 + bn];
            uint4 t;
            t.x = f2tf32(src[0]);
            t.y = f2tf32(src[(size_t)N]);
            t.z = f2tf32(src[(size_t)2 * N]);
            t.w = f2tf32(src[(size_t)3 * N]);
            *(uint4*)&Bsn[bn * APITCH + kq * 4] = t;
        }
        __syncthreads();

#pragma unroll
        for (int kk = 0; kk < 4; kk++) {
            uint32_t af[4][4], bf[4][2];
#pragma unroll
            for (int mt = 0; mt < 4; mt++) {
                uint32_t addr = as_base +
                    ((a_row + mt * 16) * APITCH + kk * 8 + a_k) * 4;
                ldsm_x4(af[mt][0], af[mt][1], af[mt][2], af[mt][3], addr);
            }
#pragma unroll
            for (int bt = 0; bt < 2; bt++) {
                uint32_t addr = bs_base +
                    ((b_row + bt * 16) * APITCH + kk * 8 + b_k) * 4;
                ldsm_x4(bf[bt * 2][0], bf[bt * 2][1],
                        bf[bt * 2 + 1][0], bf[bt * 2 + 1][1], addr);
            }
#pragma unroll
            for (int mt = 0; mt < 4; mt++)
#pragma unroll
                for (int nt = 0; nt < 4; nt++)
                    mma_tf32(acc[mt][nt], af[mt][0], af[mt][1], af[mt][2],
                             af[mt][3], bf[nt][0], bf[nt][1]);
        }
        __syncthreads();
    }

    // ---- epilogue ----
    const int gid = lane >> 2, tig = lane & 3;
#pragma unroll
    for (int mt = 0; mt < 4; mt++) {
        int row = m0 + m0w + mt * 16 + gid;
#pragma unroll
        for (int nt = 0; nt < 4; nt++) {
            int col = n0 + n0w + nt * 8 + tig * 2;
            float2 v0, v1;
            v0.x = acc[mt][nt][0]; v0.y = acc[mt][nt][1];
            v1.x = acc[mt][nt][2]; v1.y = acc[mt][nt][3];
            if (bias) {
                float2 bv = *(const float2*)&bias[col];
                v0.x += bv.x; v0.y += bv.y;
                v1.x += bv.x; v1.y += bv.y;
            }
            *(float2*)&Cm[(size_t)row * N + col] = v0;
            *(float2*)&Cm[(size_t)(row + 8) * N + col] = v1;
        }
    }
}

// ------------- transpose interaction [b,k,q,h] -> imt[b,h,q,k] --------------
__global__ __launch_bounds__(256) void transpose_im(const float* __restrict__ im)
{
    extern __shared__ float s[];   // [512][33]
    const int tid = threadIdx.x;
    const int k0 = blockIdx.x * 32;
    const int q0 = blockIdx.y * 32;
    const int b  = blockIdx.z;
    const float* inb = im + (size_t)b * TT * TT * HH;

#pragma unroll 8
    for (int step = 0; step < 64; step++) {
        int i = tid + step * 256;
        int kk   = i >> 9;
        int rest = i & 511;
        s[rest * 33 + kk] = inb[(size_t)(k0 + kk) * (TT * HH) + q0 * HH + rest];
    }
    __syncthreads();
#pragma unroll 8
    for (int step = 0; step < 64; step++) {
        int o = tid + step * 256;
        int row = o >> 5;
        int kk  = o & 31;
        int h  = row & 15, qq = row >> 4;
        g_imt[((size_t)(b * HH + h) * TT + q0 + qq) * TT + k0 + kk] = s[row * 33 + kk];
    }
}

// ------------------- flash attention (fp32, causal, +imt) -------------------
__global__ __launch_bounds__(256, 2) void attn_kernel(const int* __restrict__ pad_mask)
{
    extern __shared__ float sm[];
    float* Qst = sm;                 // [d][q]  pitch 68 (pre-scaled)
    float* Kst = sm + 64 * 68;       // [d][k]  pitch 68
    float* Vs  = sm + 2 * 64 * 68;   // [k][d]  pitch 68
    float* Ps  = sm + 3 * 64 * 68;   // [q][k]  pitch 68

    const int tid = threadIdx.x;
    const int tx = tid & 15, ty = tid >> 4;
    const int qt = blockIdx.x, h = blockIdx.y, b = blockIdx.z;
    const int q0 = qt * 64;
    const float scale = 0.125f;

#pragma unroll
    for (int it = 0; it < 4; it++) {
        int i = tid + it * 256;
        int row = i >> 4;
        int c4  = (i & 15) * 4;
        float4 qv = *(const float4*)&g_qbuf[((size_t)(b * TT + q0 + row)) * CCH + h * DD + c4];
        Qst[(c4 + 0) * 68 + row] = qv.x * scale;
        Qst[(c4 + 1) * 68 + row] = qv.y * scale;
        Qst[(c4 + 2) * 68 + row] = qv.z * scale;
        Qst[(c4 + 3) * 68 + row] = qv.w * scale;
    }

    int rowpad[4];
#pragma unroll
    for (int i = 0; i < 4; i++) rowpad[i] = pad_mask[b * TT + q0 + ty * 4 + i];

    float m_i[4], l_i[4], acc[4][4];
#pragma unroll
    for (int i = 0; i < 4; i++) {
        m_i[i] = -INFINITY; l_i[i] = 0.f;
#pragma unroll
        for (int j = 0; j < 4; j++) acc[i][j] = 0.f;
    }

    const size_t im_base = (size_t)(b * HH + h) * TT * TT;
    const int nkt = qt + 1;

    for (int kt = 0; kt < nkt; kt++) {
        const int k0 = kt * 64;
#pragma unroll
        for (int it = 0; it < 4; it++) {
            int i = tid + it * 256;
            int row = i >> 4;
            int c4  = (i & 15) * 4;
            size_t g = ((size_t)(b * TT + k0 + row)) * CCH + h * DD + c4;
            float4 kv = *(const float4*)&g_kbuf[g];
            Kst[(c4 + 0) * 68 + row] = kv.x;
            Kst[(c4 + 1) * 68 + row] = kv.y;
            Kst[(c4 + 2) * 68 + row] = kv.z;
            Kst[(c4 + 3) * 68 + row] = kv.w;
            float4 vv = *(const float4*)&g_vbuf[g];
            *(float4*)&Vs[row * 68 + c4] = vv;
        }
        __syncthreads();

        float s4[4][4];
#pragma unroll
        for (int i = 0; i < 4; i++)
#pragma unroll
            for (int j = 0; j < 4; j++) s4[i][j] = 0.f;
#pragma unroll
        for (int d = 0; d < 64; d++) {
            float4 a4 = *(const float4*)&Qst[d * 68 + ty * 4];
            float4 b4 = *(const float4*)&Kst[d * 68 + tx * 4];
            float a[4] = {a4.x, a4.y, a4.z, a4.w};
            float bb[4] = {b4.x, b4.y, b4.z, b4.w};
#pragma unroll
            for (int i = 0; i < 4; i++)
#pragma unroll
                for (int j = 0; j < 4; j++)
                    s4[i][j] = fmaf(a[i], bb[j], s4[i][j]);
        }

#pragma unroll
        for (int i = 0; i < 4; i++) {
            int q = q0 + ty * 4 + i;
            float4 im4 = *(const float4*)&g_imt[im_base + (size_t)q * TT + k0 + tx * 4];
            float imv[4] = {im4.x, im4.y, im4.z, im4.w};
#pragma unroll
            for (int j = 0; j < 4; j++) {
                int k = k0 + tx * 4 + j;
                float v = rowpad[i] ? s4[i][j] : -1e9f;
                v = (k <= q) ? v : -INFINITY;
                s4[i][j] = v + imv[j];
            }
        }

#pragma unroll
        for (int i = 0; i < 4; i++) {
            float rm = fmaxf(fmaxf(s4[i][0], s4[i][1]), fmaxf(s4[i][2], s4[i][3]));
#pragma unroll
            for (int msk = 1; msk < 16; msk <<= 1)
                rm = fmaxf(rm, __shfl_xor_sync(0xffffffffu, rm, msk));
            float m_new = fmaxf(m_i[i], rm);
            float alpha = __expf(m_i[i] - m_new);
            float rs = 0.f;
#pragma unroll
            for (int j = 0; j < 4; j++) {
                float p = __expf(s4[i][j] - m_new);
                s4[i][j] = p;
                rs += p;
            }
#pragma unroll
            for (int msk = 1; msk < 16; msk <<= 1)
                rs += __shfl_xor_sync(0xffffffffu, rs, msk);
            l_i[i] = l_i[i] * alpha + rs;
            m_i[i] = m_new;
#pragma unroll
            for (int j = 0; j < 4; j++) acc[i][j] *= alpha;
        }

#pragma unroll
        for (int i = 0; i < 4; i++) {
            float4 pv;
            pv.x = s4[i][0]; pv.y = s4[i][1]; pv.z = s4[i][2]; pv.w = s4[i][3];
            *(float4*)&Ps[(ty * 4 + i) * 68 + tx * 4] = pv;
        }
        __syncthreads();
#pragma unroll
        for (int k = 0; k < 64; k++) {
            float4 v4 = *(const float4*)&Vs[k * 68 + tx * 4];
            float vv[4] = {v4.x, v4.y, v4.z, v4.w};
            float p0 = Ps[(ty * 4 + 0) * 68 + k];
            float p1 = Ps[(ty * 4 + 1) * 68 + k];
            float p2 = Ps[(ty * 4 + 2) * 68 + k];
            float p3 = Ps[(ty * 4 + 3) * 68 + k];
#pragma unroll
            for (int j = 0; j < 4; j++) {
                acc[0][j] = fmaf(p0, vv[j], acc[0][j]);
                acc[1][j] = fmaf(p1, vv[j], acc[1][j]);
                acc[2][j] = fmaf(p2, vv[j], acc[2][j]);
                acc[3][j] = fmaf(p3, vv[j], acc[3][j]);
            }
        }
        __syncthreads();
    }

#pragma unroll
    for (int i = 0; i < 4; i++) {
        float inv = 1.f / l_i[i];
        float4 o;
        o.x = acc[i][0] * inv; o.y = acc[i][1] * inv;
        o.z = acc[i][2] * inv; o.w = acc[i][3] * inv;
        *(float4*)&g_ctx[((size_t)(b * TT + q0 + ty * 4 + i)) * CCH + h * DD + tx * 4] = o;
    }
}

// ----------------------------- host launcher --------------------------------
extern "C" void kernel_launch(void* const* d_in, const int* in_sizes, int n_in,
                              void* d_out, int out_size)
{
    const float* x       = (const float*)d_in[0];
    const int*   pad     = (const int*)  d_in[1];
    const float* im      = (const float*)d_in[2];
    const float* W_ckv   = (const float*)d_in[3];
    const float* W_cq    = (const float*)d_in[4];
    const float* W_kc    = (const float*)d_in[5];
    const float* W_qc    = (const float*)d_in[6];
    const float* W_vc    = (const float*)d_in[7];
    const float* W_proj  = (const float*)d_in[8];
    const float* b_proj  = (const float*)d_in[9];
    float* out = (float*)d_out;

    float *kv_down, *q_down, *kbuf, *qbuf, *vbuf, *ctx;
    cudaGetSymbolAddress((void**)&kv_down, g_kv_down);
    cudaGetSymbolAddress((void**)&q_down,  g_q_down);
    cudaGetSymbolAddress((void**)&kbuf,    g_kbuf);
    cudaGetSymbolAddress((void**)&qbuf,    g_qbuf);
    cudaGetSymbolAddress((void**)&vbuf,    g_vbuf);
    cudaGetSymbolAddress((void**)&ctx,     g_ctx);

    cudaFuncSetAttribute(transpose_im, cudaFuncAttributeMaxDynamicSharedMemorySize,
                         512 * 33 * 4);
    cudaFuncSetAttribute(attn_kernel, cudaFuncAttributeMaxDynamicSharedMemorySize,
                         4 * 64 * 68 * 4);

    const int M = BB * TT;   // 4096

    // interaction transpose (independent of GEMM chain)
    transpose_im<<<dim3(32, 32, 4), 256, 512 * 33 * 4>>>(im);

    // down projections: [4096,1024] @ [1024,256]
    gemm_tf32<<<dim3(LLAT / 128, M / 128), 256>>>(x, W_ckv, kv_down, nullptr, M, LLAT, CCH);
    gemm_tf32<<<dim3(LLAT / 128, M / 128), 256>>>(x, W_cq,  q_down,  nullptr, M, LLAT, CCH);

    // up projections: [4096,256] @ [256,1024]
    gemm_tf32<<<dim3(CCH / 128, M / 128), 256>>>(kv_down, W_kc, kbuf, nullptr, M, CCH, LLAT);
    gemm_tf32<<<dim3(CCH / 128, M / 128), 256>>>(q_down,  W_qc, qbuf, nullptr, M, CCH, LLAT);
    gemm_tf32<<<dim3(CCH / 128, M / 128), 256>>>(kv_down, W_vc, vbuf, nullptr, M, CCH, LLAT);

    // attention
    attn_kernel<<<dim3(TT / 64, HH, BB), 256, 4 * 64 * 68 * 4>>>(pad);

    // output projection + bias: [4096,1024] @ [1024,1024]
    gemm_tf32<<<dim3(CCH / 128, M / 128), 256>>>(ctx, W_proj, out, b_proj, M, CCH, CCH);
}

// round 7
// speedup vs baseline: 2.1397x; 1.3546x over previous
#include <cuda_runtime.h>
#include <cuda_fp16.h>
#include <math.h>
#include <float.h>
#include <stdint.h>

#define BB 4
#define TT 1024
#define CCH 1024
#define HH 16
#define LLAT 256
#define DD 64

// ---------------- scratch (static device globals; no allocations allowed) ----
__device__ float  g_kv_down[BB * TT * LLAT];
__device__ float  g_q_down [BB * TT * LLAT];
__device__ float  g_kbuf   [BB * TT * CCH];
__device__ float  g_qbuf   [BB * TT * CCH];
__device__ float  g_vbuf   [BB * TT * CCH];
__device__ float  g_ctx    [BB * TT * CCH];
__device__ __half g_imt_h  [(size_t)BB * HH * TT * TT];  // 134 MB fp16 transposed im

// ---------------------------- tf32 helpers ----------------------------------
__device__ __forceinline__ uint32_t f2tf32(float x) {
    uint32_t r;
    asm("cvt.rna.tf32.f32 %0, %1;" : "=r"(r) : "f"(x));
    return r;
}

__device__ __forceinline__ void ldsm_x4(uint32_t& r0, uint32_t& r1, uint32_t& r2,
                                        uint32_t& r3, uint32_t addr) {
    asm volatile("ldmatrix.sync.aligned.m8n8.x4.shared.b16 {%0,%1,%2,%3}, [%4];"
                 : "=r"(r0), "=r"(r1), "=r"(r2), "=r"(r3) : "r"(addr));
}

__device__ __forceinline__ void mma_tf32(float* d, const uint32_t* a,
                                         uint32_t b0, uint32_t b1) {
    asm volatile(
        "mma.sync.aligned.m16n8k8.row.col.f32.tf32.tf32.f32 "
        "{%0,%1,%2,%3}, {%4,%5,%6,%7}, {%8,%9}, {%0,%1,%2,%3};"
        : "+f"(d[0]), "+f"(d[1]), "+f"(d[2]), "+f"(d[3])
        : "r"(a[0]), "r"(a[1]), "r"(a[2]), "r"(a[3]), "r"(b0), "r"(b1));
}

// ---------------- tf32 tensor-core GEMM: C[M,N] = A[M,K] @ B[K,N] (+bias) ----
#define APITCH 36
__global__ __launch_bounds__(256) void gemm_tf32(
    const float* __restrict__ A, const float* __restrict__ Bm,
    float* __restrict__ Cm, const float* __restrict__ bias,
    int M, int N, int K)
{
    __shared__ uint32_t As [128 * APITCH];
    __shared__ uint32_t Bsn[128 * APITCH];

    const int tid  = threadIdx.x;
    const int lane = tid & 31;
    const int warp = tid >> 5;
    const int m0 = blockIdx.y * 128, n0 = blockIdx.x * 128;
    const int m0w = (warp >> 2) * 64;
    const int n0w = (warp & 3) * 32;

    const int am  = tid >> 3;
    const int akq = tid & 7;
    const int bn  = tid & 127;
    const int bkq = tid >> 7;

    const int a_row = m0w + (lane & 15);
    const int a_k   = (lane >> 4) * 4;
    const int b_row = n0w + (lane & 7) + ((lane >> 4) & 1) * 8;
    const int b_k   = ((lane >> 3) & 1) * 4;

    const uint32_t as_base = (uint32_t)__cvta_generic_to_shared(As);
    const uint32_t bs_base = (uint32_t)__cvta_generic_to_shared(Bsn);

    float acc[4][4][4];
#pragma unroll
    for (int i = 0; i < 4; i++)
#pragma unroll
        for (int j = 0; j < 4; j++)
#pragma unroll
            for (int r = 0; r < 4; r++) acc[i][j][r] = 0.f;

    for (int k0 = 0; k0 < K; k0 += 32) {
#pragma unroll
        for (int it = 0; it < 4; it++) {
            int row = am + it * 32;
            float4 v = *(const float4*)&A[(size_t)(m0 + row) * K + k0 + akq * 4];
            uint4 t;
            t.x = f2tf32(v.x); t.y = f2tf32(v.y);
            t.z = f2tf32(v.z); t.w = f2tf32(v.w);
            *(uint4*)&As[row * APITCH + akq * 4] = t;
        }
#pragma unroll
        for (int it = 0; it < 4; it++) {
            int kq = bkq + it * 2;
            const float* src = &Bm[(size_t)(k0 + kq * 4) * N + n0 + bn];
            uint4 t;
            t.x = f2tf32(src[0]);
            t.y = f2tf32(src[(size_t)N]);
            t.z = f2tf32(src[(size_t)2 * N]);
            t.w = f2tf32(src[(size_t)3 * N]);
            *(uint4*)&Bsn[bn * APITCH + kq * 4] = t;
        }
        __syncthreads();

#pragma unroll
        for (int kk = 0; kk < 4; kk++) {
            uint32_t af[4][4], bf[4][2];
#pragma unroll
            for (int mt = 0; mt < 4; mt++) {
                uint32_t addr = as_base +
                    ((a_row + mt * 16) * APITCH + kk * 8 + a_k) * 4;
                ldsm_x4(af[mt][0], af[mt][1], af[mt][2], af[mt][3], addr);
            }
#pragma unroll
            for (int bt = 0; bt < 2; bt++) {
                uint32_t addr = bs_base +
                    ((b_row + bt * 16) * APITCH + kk * 8 + b_k) * 4;
                ldsm_x4(bf[bt * 2][0], bf[bt * 2][1],
                        bf[bt * 2 + 1][0], bf[bt * 2 + 1][1], addr);
            }
#pragma unroll
            for (int mt = 0; mt < 4; mt++)
#pragma unroll
                for (int nt = 0; nt < 4; nt++)
                    mma_tf32(acc[mt][nt], af[mt], bf[nt][0], bf[nt][1]);
        }
        __syncthreads();
    }

    const int gid = lane >> 2, tig = lane & 3;
#pragma unroll
    for (int mt = 0; mt < 4; mt++) {
        int row = m0 + m0w + mt * 16 + gid;
#pragma unroll
        for (int nt = 0; nt < 4; nt++) {
            int col = n0 + n0w + nt * 8 + tig * 2;
            float2 v0, v1;
            v0.x = acc[mt][nt][0]; v0.y = acc[mt][nt][1];
            v1.x = acc[mt][nt][2]; v1.y = acc[mt][nt][3];
            if (bias) {
                float2 bv = *(const float2*)&bias[col];
                v0.x += bv.x; v0.y += bv.y;
                v1.x += bv.x; v1.y += bv.y;
            }
            *(float2*)&Cm[(size_t)row * N + col] = v0;
            *(float2*)&Cm[(size_t)(row + 8) * N + col] = v1;
        }
    }
}

// ------ transpose interaction [b,k,q,h] -> imt[b,h,q,k] (fp16 output) -------
__global__ __launch_bounds__(256) void transpose_im(const float* __restrict__ im)
{
    extern __shared__ float s[];   // [512][33]
    const int tid = threadIdx.x;
    const int k0 = blockIdx.x * 32;
    const int q0 = blockIdx.y * 32;
    const int b  = blockIdx.z;
    const float* inb = im + (size_t)b * TT * TT * HH;

#pragma unroll 8
    for (int step = 0; step < 64; step++) {
        int i = tid + step * 256;
        int kk   = i >> 9;
        int rest = i & 511;
        s[rest * 33 + kk] = inb[(size_t)(k0 + kk) * (TT * HH) + q0 * HH + rest];
    }
    __syncthreads();
#pragma unroll 8
    for (int step = 0; step < 32; step++) {
        int o = tid + step * 256;          // 0..8191 : (row 0..511) x (kk2 0..15)
        int row = o >> 4;
        int kk2 = (o & 15) * 2;
        int h  = row & 15, qq = row >> 4;
        __half2 v = __floats2half2_rn(s[row * 33 + kk2], s[row * 33 + kk2 + 1]);
        *(__half2*)&g_imt_h[((size_t)(b * HH + h) * TT + q0 + qq) * TT + k0 + kk2] = v;
    }
}

// ------------- flash attention on tf32 mma (causal, pad, +imt fp16) ---------
// q-tile 128 per block; 8 warps x 16 q-rows; k-tiles of 64.
#define PITCH 68
#define ATT_SMEM ((128 + 64 + 64) * PITCH * 4)
__global__ __launch_bounds__(256) void attn_mma(const int* __restrict__ pad_mask)
{
    extern __shared__ uint32_t smx[];
    uint32_t* Qs = smx;                  // 128 x PITCH (reused as Ps, warp-private rows)
    uint32_t* Ks = smx + 128 * PITCH;    // 64 x PITCH  [key][d]
    uint32_t* Vt = Ks + 64 * PITCH;      // 64 x PITCH  [d][key]

    const int tid = threadIdx.x, lane = tid & 31, w = tid >> 5;
    const int bx = blockIdx.x, h = blockIdx.y, b = blockIdx.z;
    const int q0 = bx * 128;
    const int gid = lane >> 2, tig = lane & 3;
    const int qw = q0 + w * 16;          // warp's first q row
    const int r0 = qw + gid, r1 = r0 + 8;

    const uint32_t qs_base = (uint32_t)__cvta_generic_to_shared(Qs);
    const uint32_t ks_base = (uint32_t)__cvta_generic_to_shared(Ks);
    const uint32_t vt_base = (uint32_t)__cvta_generic_to_shared(Vt);

    // ---- stage Q (pre-scaled by D^-0.5) ----
#pragma unroll
    for (int it = 0; it < 8; it++) {
        int idx = tid + it * 256;            // 0..2047 = 128 rows x 16 float4
        int row = idx >> 4;
        int f4  = (idx & 15) * 4;
        float4 v = *(const float4*)&g_qbuf[((size_t)(b * TT + q0 + row)) * CCH + h * DD + f4];
        uint4 t;
        t.x = f2tf32(v.x * 0.125f); t.y = f2tf32(v.y * 0.125f);
        t.z = f2tf32(v.z * 0.125f); t.w = f2tf32(v.w * 0.125f);
        *(uint4*)&Qs[row * PITCH + f4] = t;
    }
    __syncthreads();

    // ---- Q a-fragments (kept in registers; Qs space becomes Ps) ----
    const int a_row  = w * 16 + (lane & 15);
    const int a_koff = (lane >> 4) * 4;
    const int b_row  = (lane & 7) + ((lane >> 4) & 1) * 8;
    const int b_koff = ((lane >> 3) & 1) * 4;

    uint32_t qf[8][4];
#pragma unroll
    for (int kc = 0; kc < 8; kc++)
        ldsm_x4(qf[kc][0], qf[kc][1], qf[kc][2], qf[kc][3],
                qs_base + (a_row * PITCH + kc * 8 + a_koff) * 4);

    const int pad0 = pad_mask[b * TT + r0];
    const int pad1 = pad_mask[b * TT + r1];
    const __half* imr0 = &g_imt_h[((size_t)(b * HH + h) * TT + r0) * TT];
    const __half* imr1 = &g_imt_h[((size_t)(b * HH + h) * TT + r1) * TT];

    float m0 = -INFINITY, m1 = -INFINITY, l0 = 0.f, l1 = 0.f;
    float o[8][4];
#pragma unroll
    for (int nt = 0; nt < 8; nt++)
#pragma unroll
        for (int r = 0; r < 4; r++) o[nt][r] = 0.f;

    const int nkt = 2 * bx + 2;
    for (int kt = 0; kt < nkt; kt++) {
        const int k0 = kt * 64;
        __syncthreads();                 // previous tile's reads complete
        // ---- stage K [key][d] and V transposed [d][key] ----
#pragma unroll
        for (int it = 0; it < 4; it++) {
            int idx = tid + it * 256;        // 64 rows x 16 float4
            int row = idx >> 4;
            int f4  = (idx & 15) * 4;
            size_t g = ((size_t)(b * TT + k0 + row)) * CCH + h * DD + f4;
            float4 kv = *(const float4*)&g_kbuf[g];
            uint4 t;
            t.x = f2tf32(kv.x); t.y = f2tf32(kv.y);
            t.z = f2tf32(kv.z); t.w = f2tf32(kv.w);
            *(uint4*)&Ks[row * PITCH + f4] = t;
            float4 vv = *(const float4*)&g_vbuf[g];
            Vt[(f4 + 0) * PITCH + row] = f2tf32(vv.x);
            Vt[(f4 + 1) * PITCH + row] = f2tf32(vv.y);
            Vt[(f4 + 2) * PITCH + row] = f2tf32(vv.z);
            Vt[(f4 + 3) * PITCH + row] = f2tf32(vv.w);
        }
        __syncthreads();

        if (k0 > qw + 15) continue;      // tile entirely above diagonal for this warp
        const bool partial = (k0 + 63 > qw);

        // ---- S = Q K^T ----
        float sacc[8][4];
#pragma unroll
        for (int nt = 0; nt < 8; nt++)
#pragma unroll
            for (int r = 0; r < 4; r++) sacc[nt][r] = 0.f;
#pragma unroll
        for (int kc = 0; kc < 8; kc++) {
            uint32_t bf[8][2];
#pragma unroll
            for (int g = 0; g < 4; g++)
                ldsm_x4(bf[2 * g][0], bf[2 * g][1], bf[2 * g + 1][0], bf[2 * g + 1][1],
                        ks_base + ((g * 16 + b_row) * PITCH + kc * 8 + b_koff) * 4);
#pragma unroll
            for (int nt = 0; nt < 8; nt++)
                mma_tf32(sacc[nt], qf[kc], bf[nt][0], bf[nt][1]);
        }

        // ---- mask + interaction + online softmax ----
        float rm0 = -INFINITY, rm1 = -INFINITY;
#pragma unroll
        for (int nt = 0; nt < 8; nt++) {
            int kc0 = k0 + nt * 8 + tig * 2;
            float c0 = sacc[nt][0], c1 = sacc[nt][1];
            float c2 = sacc[nt][2], c3 = sacc[nt][3];
            if (!pad0) { c0 = -1e9f; c1 = -1e9f; }
            if (!pad1) { c2 = -1e9f; c3 = -1e9f; }
            if (partial) {
                if (kc0     > r0) c0 = -INFINITY;
                if (kc0 + 1 > r0) c1 = -INFINITY;
                if (kc0     > r1) c2 = -INFINITY;
                if (kc0 + 1 > r1) c3 = -INFINITY;
            }
            float2 f0 = __half22float2(*(const __half2*)&imr0[kc0]);
            float2 f1 = __half22float2(*(const __half2*)&imr1[kc0]);
            c0 += f0.x; c1 += f0.y; c2 += f1.x; c3 += f1.y;
            sacc[nt][0] = c0; sacc[nt][1] = c1; sacc[nt][2] = c2; sacc[nt][3] = c3;
            rm0 = fmaxf(rm0, fmaxf(c0, c1));
            rm1 = fmaxf(rm1, fmaxf(c2, c3));
        }
        rm0 = fmaxf(rm0, __shfl_xor_sync(0xffffffffu, rm0, 1));
        rm0 = fmaxf(rm0, __shfl_xor_sync(0xffffffffu, rm0, 2));
        rm1 = fmaxf(rm1, __shfl_xor_sync(0xffffffffu, rm1, 1));
        rm1 = fmaxf(rm1, __shfl_xor_sync(0xffffffffu, rm1, 2));
        float mn0 = fmaxf(m0, rm0), mn1 = fmaxf(m1, rm1);
        float al0 = __expf(m0 - mn0), al1 = __expf(m1 - mn1);
        float rs0 = 0.f, rs1 = 0.f;

        uint32_t* prow0 = &Qs[(w * 16 + gid) * PITCH];
        uint32_t* prow1 = &Qs[(w * 16 + gid + 8) * PITCH];
#pragma unroll
        for (int nt = 0; nt < 8; nt++) {
            float p0 = __expf(sacc[nt][0] - mn0);
            float p1 = __expf(sacc[nt][1] - mn0);
            float p2 = __expf(sacc[nt][2] - mn1);
            float p3 = __expf(sacc[nt][3] - mn1);
            rs0 += p0 + p1; rs1 += p2 + p3;
            uint2 v0, v1;
            v0.x = f2tf32(p0); v0.y = f2tf32(p1);
            v1.x = f2tf32(p2); v1.y = f2tf32(p3);
            *(uint2*)&prow0[nt * 8 + tig * 2] = v0;
            *(uint2*)&prow1[nt * 8 + tig * 2] = v1;
        }
        rs0 += __shfl_xor_sync(0xffffffffu, rs0, 1);
        rs0 += __shfl_xor_sync(0xffffffffu, rs0, 2);
        rs1 += __shfl_xor_sync(0xffffffffu, rs1, 1);
        rs1 += __shfl_xor_sync(0xffffffffu, rs1, 2);
        l0 = l0 * al0 + rs0; m0 = mn0;
        l1 = l1 * al1 + rs1; m1 = mn1;
#pragma unroll
        for (int nt = 0; nt < 8; nt++) {
            o[nt][0] *= al0; o[nt][1] *= al0;
            o[nt][2] *= al1; o[nt][3] *= al1;
        }
        __syncwarp();    // Ps rows are warp-private; warp-level sync suffices

        // ---- O += P V ----
#pragma unroll
        for (int kc = 0; kc < 8; kc++) {
            uint32_t pf[4];
            ldsm_x4(pf[0], pf[1], pf[2], pf[3],
                    qs_base + (a_row * PITCH + kc * 8 + a_koff) * 4);
            uint32_t vf[8][2];
#pragma unroll
            for (int g = 0; g < 4; g++)
                ldsm_x4(vf[2 * g][0], vf[2 * g][1], vf[2 * g + 1][0], vf[2 * g + 1][1],
                        vt_base + ((g * 16 + b_row) * PITCH + kc * 8 + b_koff) * 4);
#pragma unroll
            for (int nt = 0; nt < 8; nt++)
                mma_tf32(o[nt], pf, vf[nt][0], vf[nt][1]);
        }
    }

    // ---- epilogue ----
    float il0 = 1.f / l0, il1 = 1.f / l1;
#pragma unroll
    for (int nt = 0; nt < 8; nt++) {
        int col = h * DD + nt * 8 + tig * 2;
        float2 v0, v1;
        v0.x = o[nt][0] * il0; v0.y = o[nt][1] * il0;
        v1.x = o[nt][2] * il1; v1.y = o[nt][3] * il1;
        *(float2*)&g_ctx[((size_t)(b * TT + r0)) * CCH + col] = v0;
        *(float2*)&g_ctx[((size_t)(b * TT + r1)) * CCH + col] = v1;
    }
}

// ----------------------------- host launcher --------------------------------
extern "C" void kernel_launch(void* const* d_in, const int* in_sizes, int n_in,
                              void* d_out, int out_size)
{
    const float* x       = (const float*)d_in[0];
    const int*   pad     = (const int*)  d_in[1];
    const float* im      = (const float*)d_in[2];
    const float* W_ckv   = (const float*)d_in[3];
    const float* W_cq    = (const float*)d_in[4];
    const float* W_kc    = (const float*)d_in[5];
    const float* W_qc    = (const float*)d_in[6];
    const float* W_vc    = (const float*)d_in[7];
    const float* W_proj  = (const float*)d_in[8];
    const float* b_proj  = (const float*)d_in[9];
    float* out = (float*)d_out;

    float *kv_down, *q_down, *kbuf, *qbuf, *vbuf, *ctx;
    cudaGetSymbolAddress((void**)&kv_down, g_kv_down);
    cudaGetSymbolAddress((void**)&q_down,  g_q_down);
    cudaGetSymbolAddress((void**)&kbuf,    g_kbuf);
    cudaGetSymbolAddress((void**)&qbuf,    g_qbuf);
    cudaGetSymbolAddress((void**)&vbuf,    g_vbuf);
    cudaGetSymbolAddress((void**)&ctx,     g_ctx);

    cudaFuncSetAttribute(transpose_im, cudaFuncAttributeMaxDynamicSharedMemorySize,
                         512 * 33 * 4);
    cudaFuncSetAttribute(attn_mma, cudaFuncAttributeMaxDynamicSharedMemorySize,
                         ATT_SMEM);

    const int M = BB * TT;   // 4096

    transpose_im<<<dim3(32, 32, 4), 256, 512 * 33 * 4>>>(im);

    gemm_tf32<<<dim3(LLAT / 128, M / 128), 256>>>(x, W_ckv, kv_down, nullptr, M, LLAT, CCH);
    gemm_tf32<<<dim3(LLAT / 128, M / 128), 256>>>(x, W_cq,  q_down,  nullptr, M, LLAT, CCH);

    gemm_tf32<<<dim3(CCH / 128, M / 128), 256>>>(kv_down, W_kc, kbuf, nullptr, M, CCH, LLAT);
    gemm_tf32<<<dim3(CCH / 128, M / 128), 256>>>(q_down,  W_qc, qbuf, nullptr, M, CCH, LLAT);
    gemm_tf32<<<dim3(CCH / 128, M / 128), 256>>>(kv_down, W_vc, vbuf, nullptr, M, CCH, LLAT);

    attn_mma<<<dim3(TT / 128, HH, BB), 256, ATT_SMEM>>>(pad);

    gemm_tf32<<<dim3(CCH / 128, M / 128), 256>>>(ctx, W_proj, out, b_proj, M, CCH, CCH);
}

// round 12
// speedup vs baseline: 2.7743x; 1.2966x over previous
#include <cuda_runtime.h>
#include <cuda_fp16.h>
#include <math.h>
#include <float.h>
#include <stdint.h>

#define BB 4
#define TT 1024
#define CCH 1024
#define HH 16
#define LLAT 256
#define DD 64

// ---------------- scratch (static device globals; no allocations allowed) ----
__device__ float  g_kv_down[BB * TT * LLAT];
__device__ float  g_q_down [BB * TT * LLAT];
__device__ float  g_kbuf   [BB * TT * CCH];
__device__ float  g_qbuf   [BB * TT * CCH];
__device__ float  g_vbuf   [BB * TT * CCH];
__device__ float  g_ctx    [BB * TT * CCH];
__device__ __half g_imt_h  [(size_t)BB * HH * TT * TT];  // 134 MB fp16 transposed im

// ---------------------------- tf32 helpers ----------------------------------
__device__ __forceinline__ uint32_t f2tf32(float x) {
    uint32_t r;
    asm("cvt.rna.tf32.f32 %0, %1;" : "=r"(r) : "f"(x));
    return r;
}

__device__ __forceinline__ void ldsm_x4(uint32_t& r0, uint32_t& r1, uint32_t& r2,
                                        uint32_t& r3, uint32_t addr) {
    asm volatile("ldmatrix.sync.aligned.m8n8.x4.shared.b16 {%0,%1,%2,%3}, [%4];"
                 : "=r"(r0), "=r"(r1), "=r"(r2), "=r"(r3) : "r"(addr));
}

__device__ __forceinline__ void mma_tf32(float* d, const uint32_t* a,
                                         uint32_t b0, uint32_t b1) {
    asm volatile(
        "mma.sync.aligned.m16n8k8.row.col.f32.tf32.tf32.f32 "
        "{%0,%1,%2,%3}, {%4,%5,%6,%7}, {%8,%9}, {%0,%1,%2,%3};"
        : "+f"(d[0]), "+f"(d[1]), "+f"(d[2]), "+f"(d[3])
        : "r"(a[0]), "r"(a[1]), "r"(a[2]), "r"(a[3]), "r"(b0), "r"(b1));
}

// --------------- pipelined tf32 GEMM, multi-job via blockIdx.z ---------------
// C[M,N] = A[M,K] @ B[K,N] (+bias). Tile 128x128, k-chunk 32, 2-stage smem
// double buffer + register prefetch; one __syncthreads per k-iteration.
struct Job  { const float* A; const float* B; float* C; };
struct Job3 { Job j[3]; };

#define APITCH 36
#define STAGE_W (128 * APITCH)             // words per matrix per stage
#define GEMM_SMEM (4 * STAGE_W * 4)        // bytes: 2 stages x (A + B)

__global__ __launch_bounds__(256) void gemm_tf32_pipe(
    Job3 jobs, const float* __restrict__ bias, int M, int N, int K)
{
    extern __shared__ uint32_t dynsm[];
    uint32_t* Asm = dynsm;                 // [stage][128*APITCH]
    uint32_t* Bsm = dynsm + 2 * STAGE_W;

    const Job jb = jobs.j[blockIdx.z];
    const float* __restrict__ A  = jb.A;
    const float* __restrict__ Bm = jb.B;
    float* __restrict__ Cm = jb.C;

    const int tid  = threadIdx.x;
    const int lane = tid & 31;
    const int warp = tid >> 5;
    const int m0 = blockIdx.y * 128, n0 = blockIdx.x * 128;
    const int m0w = (warp >> 2) * 64;
    const int n0w = (warp & 3) * 32;

    const int am  = tid >> 3;          // A row group 0..31
    const int akq = tid & 7;           // A k-quad
    const int bn  = tid & 127;         // B n
    const int bkq = tid >> 7;          // B k-quad base

    const int a_row = m0w + (lane & 15);
    const int a_k   = (lane >> 4) * 4;
    const int b_row = n0w + (lane & 7) + ((lane >> 4) & 1) * 8;
    const int b_k   = ((lane >> 3) & 1) * 4;

    const uint32_t as_base = (uint32_t)__cvta_generic_to_shared(Asm);
    const uint32_t bs_base = (uint32_t)__cvta_generic_to_shared(Bsm);

    float acc[4][4][4];
#pragma unroll
    for (int i = 0; i < 4; i++)
#pragma unroll
        for (int j = 0; j < 4; j++)
#pragma unroll
            for (int r = 0; r < 4; r++) acc[i][j][r] = 0.f;

    float4 aR[4];
    float  bR[4][4];

    // ---- prefetch / store helpers ----
    auto loadRegs = [&](int k0) {
#pragma unroll
        for (int it = 0; it < 4; it++)
            aR[it] = *(const float4*)&A[(size_t)(m0 + am + it * 32) * K + k0 + akq * 4];
#pragma unroll
        for (int it = 0; it < 4; it++) {
            int kq = bkq + it * 2;
            const float* src = &Bm[(size_t)(k0 + kq * 4) * N + n0 + bn];
            bR[it][0] = src[0];
            bR[it][1] = src[(size_t)N];
            bR[it][2] = src[(size_t)2 * N];
            bR[it][3] = src[(size_t)3 * N];
        }
    };
    auto storeRegs = [&](int stage) {
        uint32_t* As = Asm + stage * STAGE_W;
        uint32_t* Bs = Bsm + stage * STAGE_W;
#pragma unroll
        for (int it = 0; it < 4; it++) {
            uint4 t;
            t.x = f2tf32(aR[it].x); t.y = f2tf32(aR[it].y);
            t.z = f2tf32(aR[it].z); t.w = f2tf32(aR[it].w);
            *(uint4*)&As[(am + it * 32) * APITCH + akq * 4] = t;
        }
#pragma unroll
        for (int it = 0; it < 4; it++) {
            int kq = bkq + it * 2;
            uint4 t;
            t.x = f2tf32(bR[it][0]); t.y = f2tf32(bR[it][1]);
            t.z = f2tf32(bR[it][2]); t.w = f2tf32(bR[it][3]);
            *(uint4*)&Bs[bn * APITCH + kq * 4] = t;
        }
    };

    // ---- prologue ----
    loadRegs(0);
    storeRegs(0);
    __syncthreads();

    const int nIter = K >> 5;
    for (int it = 0; it < nIter; it++) {
        const int stage = it & 1;
        if (it + 1 < nIter) loadRegs((it + 1) * 32);   // issue early

        const uint32_t a_st = as_base + stage * STAGE_W * 4;
        const uint32_t b_st = bs_base + stage * STAGE_W * 4;
#pragma unroll
        for (int kk = 0; kk < 4; kk++) {
            uint32_t af[4][4], bf[4][2];
#pragma unroll
            for (int mt = 0; mt < 4; mt++)
                ldsm_x4(af[mt][0], af[mt][1], af[mt][2], af[mt][3],
                        a_st + ((a_row + mt * 16) * APITCH + kk * 8 + a_k) * 4);
#pragma unroll
            for (int bt = 0; bt < 2; bt++)
                ldsm_x4(bf[bt * 2][0], bf[bt * 2][1],
                        bf[bt * 2 + 1][0], bf[bt * 2 + 1][1],
                        b_st + ((b_row + bt * 16) * APITCH + kk * 8 + b_k) * 4);
#pragma unroll
            for (int mt = 0; mt < 4; mt++)
#pragma unroll
                for (int nt = 0; nt < 4; nt++)
                    mma_tf32(acc[mt][nt], af[mt], bf[nt][0], bf[nt][1]);
        }
        if (it + 1 < nIter) storeRegs(stage ^ 1);
        __syncthreads();
    }

    // ---- epilogue ----
    const int gid = lane >> 2, tig = lane & 3;
#pragma unroll
    for (int mt = 0; mt < 4; mt++) {
        int row = m0 + m0w + mt * 16 + gid;
#pragma unroll
        for (int nt = 0; nt < 4; nt++) {
            int col = n0 + n0w + nt * 8 + tig * 2;
            float2 v0, v1;
            v0.x = acc[mt][nt][0]; v0.y = acc[mt][nt][1];
            v1.x = acc[mt][nt][2]; v1.y = acc[mt][nt][3];
            if (bias) {
                float2 bv = *(const float2*)&bias[col];
                v0.x += bv.x; v0.y += bv.y;
                v1.x += bv.x; v1.y += bv.y;
            }
            *(float2*)&Cm[(size_t)row * N + col] = v0;
            *(float2*)&Cm[(size_t)(row + 8) * N + col] = v1;
        }
    }
}

// ------ transpose interaction [b,k,q,h] -> imt[b,h,q,k] (fp16 output) -------
__global__ __launch_bounds__(256) void transpose_im(const float* __restrict__ im)
{
    extern __shared__ float s[];   // [512][33]
    const int tid = threadIdx.x;
    const int k0 = blockIdx.x * 32;
    const int q0 = blockIdx.y * 32;
    const int b  = blockIdx.z;
    const float* inb = im + (size_t)b * TT * TT * HH;

#pragma unroll 8
    for (int step = 0; step < 64; step++) {
        int i = tid + step * 256;
        int kk   = i >> 9;
        int rest = i & 511;
        s[rest * 33 + kk] = inb[(size_t)(k0 + kk) * (TT * HH) + q0 * HH + rest];
    }
    __syncthreads();
#pragma unroll 8
    for (int step = 0; step < 32; step++) {
        int o = tid + step * 256;
        int row = o >> 4;
        int kk2 = (o & 15) * 2;
        int h  = row & 15, qq = row >> 4;
        __half2 v = __floats2half2_rn(s[row * 33 + kk2], s[row * 33 + kk2 + 1]);
        *(__half2*)&g_imt_h[((size_t)(b * HH + h) * TT + q0 + qq) * TT + k0 + kk2] = v;
    }
}

// ------------- flash attention on tf32 mma (causal, pad, +imt fp16) ---------
#define PITCH 68
#define ATT_SMEM ((128 + 64 + 64) * PITCH * 4)
__global__ __launch_bounds__(256) void attn_mma(const int* __restrict__ pad_mask)
{
    extern __shared__ uint32_t smx[];
    uint32_t* Qs = smx;                  // 128 x PITCH (reused as Ps, warp-private rows)
    uint32_t* Ks = smx + 128 * PITCH;    // 64 x PITCH  [key][d]
    uint32_t* Vt = Ks + 64 * PITCH;      // 64 x PITCH  [d][key]

    const int tid = threadIdx.x, lane = tid & 31, w = tid >> 5;
    const int bx = blockIdx.x, h = blockIdx.y, b = blockIdx.z;
    const int q0 = bx * 128;
    const int gid = lane >> 2, tig = lane & 3;
    const int qw = q0 + w * 16;
    const int r0 = qw + gid, r1 = r0 + 8;

    const uint32_t qs_base = (uint32_t)__cvta_generic_to_shared(Qs);
    const uint32_t ks_base = (uint32_t)__cvta_generic_to_shared(Ks);
    const uint32_t vt_base = (uint32_t)__cvta_generic_to_shared(Vt);

#pragma unroll
    for (int it = 0; it < 8; it++) {
        int idx = tid + it * 256;
        int row = idx >> 4;
        int f4  = (idx & 15) * 4;
        float4 v = *(const float4*)&g_qbuf[((size_t)(b * TT + q0 + row)) * CCH + h * DD + f4];
        uint4 t;
        t.x = f2tf32(v.x * 0.125f); t.y = f2tf32(v.y * 0.125f);
        t.z = f2tf32(v.z * 0.125f); t.w = f2tf32(v.w * 0.125f);
        *(uint4*)&Qs[row * PITCH + f4] = t;
    }
    __syncthreads();

    const int a_row  = w * 16 + (lane & 15);
    const int a_koff = (lane >> 4) * 4;
    const int b_row  = (lane & 7) + ((lane >> 4) & 1) * 8;
    const int b_koff = ((lane >> 3) & 1) * 4;

    uint32_t qf[8][4];
#pragma unroll
    for (int kc = 0; kc < 8; kc++)
        ldsm_x4(qf[kc][0], qf[kc][1], qf[kc][2], qf[kc][3],
                qs_base + (a_row * PITCH + kc * 8 + a_koff) * 4);

    const int pad0 = pad_mask[b * TT + r0];
    const int pad1 = pad_mask[b * TT + r1];
    const __half* imr0 = &g_imt_h[((size_t)(b * HH + h) * TT + r0) * TT];
    const __half* imr1 = &g_imt_h[((size_t)(b * HH + h) * TT + r1) * TT];

    float m0 = -INFINITY, m1 = -INFINITY, l0 = 0.f, l1 = 0.f;
    float o[8][4];
#pragma unroll
    for (int nt = 0; nt < 8; nt++)
#pragma unroll
        for (int r = 0; r < 4; r++) o[nt][r] = 0.f;

    const int nkt = 2 * bx + 2;
    for (int kt = 0; kt < nkt; kt++) {
        const int k0 = kt * 64;
        __syncthreads();
#pragma unroll
        for (int it = 0; it < 4; it++) {
            int idx = tid + it * 256;
            int row = idx >> 4;
            int f4  = (idx & 15) * 4;
            size_t g = ((size_t)(b * TT + k0 + row)) * CCH + h * DD + f4;
            float4 kv = *(const float4*)&g_kbuf[g];
            uint4 t;
            t.x = f2tf32(kv.x); t.y = f2tf32(kv.y);
            t.z = f2tf32(kv.z); t.w = f2tf32(kv.w);
            *(uint4*)&Ks[row * PITCH + f4] = t;
            float4 vv = *(const float4*)&g_vbuf[g];
            Vt[(f4 + 0) * PITCH + row] = f2tf32(vv.x);
            Vt[(f4 + 1) * PITCH + row] = f2tf32(vv.y);
            Vt[(f4 + 2) * PITCH + row] = f2tf32(vv.z);
            Vt[(f4 + 3) * PITCH + row] = f2tf32(vv.w);
        }
        __syncthreads();

        if (k0 > qw + 15) continue;
        const bool partial = (k0 + 63 > qw);

        float sacc[8][4];
#pragma unroll
        for (int nt = 0; nt < 8; nt++)
#pragma unroll
            for (int r = 0; r < 4; r++) sacc[nt][r] = 0.f;
#pragma unroll
        for (int kc = 0; kc < 8; kc++) {
            uint32_t bf[8][2];
#pragma unroll
            for (int g = 0; g < 4; g++)
                ldsm_x4(bf[2 * g][0], bf[2 * g][1], bf[2 * g + 1][0], bf[2 * g + 1][1],
                        ks_base + ((g * 16 + b_row) * PITCH + kc * 8 + b_koff) * 4);
#pragma unroll
            for (int nt = 0; nt < 8; nt++)
                mma_tf32(sacc[nt], qf[kc], bf[nt][0], bf[nt][1]);
        }

        float rm0 = -INFINITY, rm1 = -INFINITY;
#pragma unroll
        for (int nt = 0; nt < 8; nt++) {
            int kc0 = k0 + nt * 8 + tig * 2;
            float c0 = sacc[nt][0], c1 = sacc[nt][1];
            float c2 = sacc[nt][2], c3 = sacc[nt][3];
            if (!pad0) { c0 = -1e9f; c1 = -1e9f; }
            if (!pad1) { c2 = -1e9f; c3 = -1e9f; }
            if (partial) {
                if (kc0     > r0) c0 = -INFINITY;
                if (kc0 + 1 > r0) c1 = -INFINITY;
                if (kc0     > r1) c2 = -INFINITY;
                if (kc0 + 1 > r1) c3 = -INFINITY;
            }
            float2 f0 = __half22float2(*(const __half2*)&imr0[kc0]);
            float2 f1 = __half22float2(*(const __half2*)&imr1[kc0]);
            c0 += f0.x; c1 += f0.y; c2 += f1.x; c3 += f1.y;
            sacc[nt][0] = c0; sacc[nt][1] = c1; sacc[nt][2] = c2; sacc[nt][3] = c3;
            rm0 = fmaxf(rm0, fmaxf(c0, c1));
            rm1 = fmaxf(rm1, fmaxf(c2, c3));
        }
        rm0 = fmaxf(rm0, __shfl_xor_sync(0xffffffffu, rm0, 1));
        rm0 = fmaxf(rm0, __shfl_xor_sync(0xffffffffu, rm0, 2));
        rm1 = fmaxf(rm1, __shfl_xor_sync(0xffffffffu, rm1, 1));
        rm1 = fmaxf(rm1, __shfl_xor_sync(0xffffffffu, rm1, 2));
        float mn0 = fmaxf(m0, rm0), mn1 = fmaxf(m1, rm1);
        float al0 = __expf(m0 - mn0), al1 = __expf(m1 - mn1);
        float rs0 = 0.f, rs1 = 0.f;

        uint32_t* prow0 = &Qs[(w * 16 + gid) * PITCH];
        uint32_t* prow1 = &Qs[(w * 16 + gid + 8) * PITCH];
#pragma unroll
        for (int nt = 0; nt < 8; nt++) {
            float p0 = __expf(sacc[nt][0] - mn0);
            float p1 = __expf(sacc[nt][1] - mn0);
            float p2 = __expf(sacc[nt][2] - mn1);
            float p3 = __expf(sacc[nt][3] - mn1);
            rs0 += p0 + p1; rs1 += p2 + p3;
            uint2 v0, v1;
            v0.x = f2tf32(p0); v0.y = f2tf32(p1);
            v1.x = f2tf32(p2); v1.y = f2tf32(p3);
            *(uint2*)&prow0[nt * 8 + tig * 2] = v0;
            *(uint2*)&prow1[nt * 8 + tig * 2] = v1;
        }
        rs0 += __shfl_xor_sync(0xffffffffu, rs0, 1);
        rs0 += __shfl_xor_sync(0xffffffffu, rs0, 2);
        rs1 += __shfl_xor_sync(0xffffffffu, rs1, 1);
        rs1 += __shfl_xor_sync(0xffffffffu, rs1, 2);
        l0 = l0 * al0 + rs0; m0 = mn0;
        l1 = l1 * al1 + rs1; m1 = mn1;
#pragma unroll
        for (int nt = 0; nt < 8; nt++) {
            o[nt][0] *= al0; o[nt][1] *= al0;
            o[nt][2] *= al1; o[nt][3] *= al1;
        }
        __syncwarp();

#pragma unroll
        for (int kc = 0; kc < 8; kc++) {
            uint32_t pf[4];
            ldsm_x4(pf[0], pf[1], pf[2], pf[3],
                    qs_base + (a_row * PITCH + kc * 8 + a_koff) * 4);
            uint32_t vf[8][2];
#pragma unroll
            for (int g = 0; g < 4; g++)
                ldsm_x4(vf[2 * g][0], vf[2 * g][1], vf[2 * g + 1][0], vf[2 * g + 1][1],
                        vt_base + ((g * 16 + b_row) * PITCH + kc * 8 + b_koff) * 4);
#pragma unroll
            for (int nt = 0; nt < 8; nt++)
                mma_tf32(o[nt], pf, vf[nt][0], vf[nt][1]);
        }
    }

    float il0 = 1.f / l0, il1 = 1.f / l1;
#pragma unroll
    for (int nt = 0; nt < 8; nt++) {
        int col = h * DD + nt * 8 + tig * 2;
        float2 v0, v1;
        v0.x = o[nt][0] * il0; v0.y = o[nt][1] * il0;
        v1.x = o[nt][2] * il1; v1.y = o[nt][3] * il1;
        *(float2*)&g_ctx[((size_t)(b * TT + r0)) * CCH + col] = v0;
        *(float2*)&g_ctx[((size_t)(b * TT + r1)) * CCH + col] = v1;
    }
}

// ----------------------------- host launcher --------------------------------
extern "C" void kernel_launch(void* const* d_in, const int* in_sizes, int n_in,
                              void* d_out, int out_size)
{
    const float* x       = (const float*)d_in[0];
    const int*   pad     = (const int*)  d_in[1];
    const float* im      = (const float*)d_in[2];
    const float* W_ckv   = (const float*)d_in[3];
    const float* W_cq    = (const float*)d_in[4];
    const float* W_kc    = (const float*)d_in[5];
    const float* W_qc    = (const float*)d_in[6];
    const float* W_vc    = (const float*)d_in[7];
    const float* W_proj  = (const float*)d_in[8];
    const float* b_proj  = (const float*)d_in[9];
    float* out = (float*)d_out;

    float *kv_down, *q_down, *kbuf, *qbuf, *vbuf, *ctx;
    cudaGetSymbolAddress((void**)&kv_down, g_kv_down);
    cudaGetSymbolAddress((void**)&q_down,  g_q_down);
    cudaGetSymbolAddress((void**)&kbuf,    g_kbuf);
    cudaGetSymbolAddress((void**)&qbuf,    g_qbuf);
    cudaGetSymbolAddress((void**)&vbuf,    g_vbuf);
    cudaGetSymbolAddress((void**)&ctx,     g_ctx);

    cudaFuncSetAttribute(gemm_tf32_pipe, cudaFuncAttributeMaxDynamicSharedMemorySize,
                         GEMM_SMEM);
    cudaFuncSetAttribute(transpose_im, cudaFuncAttributeMaxDynamicSharedMemorySize,
                         512 * 33 * 4);
    cudaFuncSetAttribute(attn_mma, cudaFuncAttributeMaxDynamicSharedMemorySize,
                         ATT_SMEM);

    const int M = BB * TT;   // 4096

    transpose_im<<<dim3(32, 32, 4), 256, 512 * 33 * 4>>>(im);

    // down projections (merged, z=2): [4096,1024] @ [1024,256]
    Job3 jd;
    jd.j[0] = { x, W_ckv, kv_down };
    jd.j[1] = { x, W_cq,  q_down  };
    jd.j[2] = { x, W_ckv, kv_down };   // unused
    gemm_tf32_pipe<<<dim3(LLAT / 128, M / 128, 2), 256, GEMM_SMEM>>>(
        jd, nullptr, M, LLAT, CCH);

    // up projections (merged, z=3): [4096,256] @ [256,1024]
    Job3 ju;
    ju.j[0] = { kv_down, W_kc, kbuf };
    ju.j[1] = { q_down,  W_qc, qbuf };
    ju.j[2] = { kv_down, W_vc, vbuf };
    gemm_tf32_pipe<<<dim3(CCH / 128, M / 128, 3), 256, GEMM_SMEM>>>(
        ju, nullptr, M, CCH, LLAT);

    attn_mma<<<dim3(TT / 128, HH, BB), 256, ATT_SMEM>>>(pad);

    // output projection + bias: [4096,1024] @ [1024,1024]
    Job3 jp;
    jp.j[0] = { ctx, W_proj, out };
    jp.j[1] = jp.j[0]; jp.j[2] = jp.j[0];
    gemm_tf32_pipe<<<dim3(CCH / 128, M / 128, 1), 256, GEMM_SMEM>>>(
        jp, b_proj, M, CCH, CCH);
}